// round 10
// baseline (speedup 1.0000x reference)
#include <cuda_runtime.h>
#include <cuda_bf16.h>
#include <cstddef>
#include <cstdint>

// ---------------------------------------------------------------------------
// dygraphSAGE on GB300 (base sm_103 target): fused CSR-gather + mma.sync
// bf16 hi/lo GEMMs (fragment-baked B, conflict-free smem, 2 CTA/SM)
// + side-stream weight prep overlap
// ---------------------------------------------------------------------------

#define D128 128
#define MAXN 131072
#define MAXE 2097152
#define SCAN_CHUNK 1024
#define MAXBLKS (MAXN / SCAN_CHUNK)   // 128

// scratch (device globals -- allocation-free per harness rules)
__device__ float g_agg  [(size_t)MAXN * D128];
__device__ float g_feat1[(size_t)MAXN * D128];
__device__ float g_feat2[(size_t)MAXN * D128];
__device__ int   g_cnt[MAXN];
__device__ int   g_off[MAXN];
__device__ int   g_cursor[MAXN];
__device__ int   g_adj[MAXE];
__device__ int   g_blocksum[MAXBLKS];
__device__ float g_Wcat[384 * D128];
__device__ int   g_is64;
// fragment-order baked weights: per plane (hi, lo): word idx
// ((ks*128 + nn)*4 + tig)*2 + w   (uint32 words, 2 bf16 each)
__device__ __align__(16) uint16_t g_B1[2 * 128 * 256];
__device__ __align__(16) uint16_t g_B2[2 * 128 * 256];
__device__ __align__(16) uint16_t g_Bf[2 * 128 * 384];

// ---------------------------------------------------------------------------
// helpers
// ---------------------------------------------------------------------------
__device__ __forceinline__ void split2(float x0, float x1, uint32_t& hi, uint32_t& lo) {
    asm("cvt.rn.bf16x2.f32 %0, %1, %2;" : "=r"(hi) : "f"(x1), "f"(x0));
    float h0 = __uint_as_float(hi << 16);
    float h1 = __uint_as_float(hi & 0xffff0000u);
    asm("cvt.rn.bf16x2.f32 %0, %1, %2;" : "=r"(lo) : "f"(x1 - h1), "f"(x0 - h0));
}

__device__ __forceinline__ void mma16816(float* c, const uint32_t* a, const uint32_t* b) {
    asm volatile("mma.sync.aligned.m16n8k16.row.col.f32.bf16.bf16.f32 "
                 "{%0,%1,%2,%3}, {%4,%5,%6,%7}, {%8,%9}, {%0,%1,%2,%3};"
                 : "+f"(c[0]), "+f"(c[1]), "+f"(c[2]), "+f"(c[3])
                 : "r"(a[0]), "r"(a[1]), "r"(a[2]), "r"(a[3]),
                   "r"(b[0]), "r"(b[1]));
}

// ---------------------------------------------------------------------------
// zero cnt + detect index dtype (block 0 samples)
// ---------------------------------------------------------------------------
__global__ void zdetect_kernel(const int* __restrict__ ei, int* __restrict__ cnt,
                               int E, int n) {
    int i = blockIdx.x * blockDim.x + threadIdx.x;
    if (i < n) cnt[i] = 0;
    if (blockIdx.x == 0) {
        __shared__ int any;
        if (threadIdx.x == 0) any = 0;
        __syncthreads();
        int c = E < 4096 ? E : 4096;
        for (int j = threadIdx.x; j < c; j += blockDim.x)
            if (ei[2 * j + 1] != 0) any = 1;
        __syncthreads();
        if (threadIdx.x == 0) g_is64 = any ? 0 : 1;
    }
}

__device__ __forceinline__ int load_idx(const void* ei, size_t pos) {
    return g_is64 ? (int)((const long long*)ei)[pos] : ((const int*)ei)[pos];
}

__global__ void deg_kernel(const void* __restrict__ ei, int* __restrict__ cnt, int E) {
    int e = blockIdx.x * blockDim.x + threadIdx.x;
    if (e < E) atomicAdd(&cnt[load_idx(ei, (size_t)E + e)], 1);
}

// ---------------------------------------------------------------------------
// 2-phase parallel exclusive scan of cnt -> off (+ cursor copy)
// ---------------------------------------------------------------------------
__global__ void scan_p1(const int* __restrict__ cnt, int* __restrict__ blocksum, int n) {
    __shared__ int red[1024];
    int b = blockIdx.x, t = threadIdx.x;
    int i = b * SCAN_CHUNK + t;
    red[t] = (i < n) ? cnt[i] : 0;
    __syncthreads();
    for (int d = 512; d > 0; d >>= 1) {
        if (t < d) red[t] += red[t + d];
        __syncthreads();
    }
    if (t == 0) blocksum[b] = red[0];
}

__global__ void scan_p3(const int* __restrict__ cnt, const int* __restrict__ blocksum,
                        int* __restrict__ off, int* __restrict__ cursor, int n, int B) {
    __shared__ int s[1024];
    __shared__ int bs[MAXBLKS];
    int b = blockIdx.x, t = threadIdx.x;
    if (t < MAXBLKS) bs[t] = (t < B) ? blocksum[t] : 0;
    __syncthreads();
    for (int d = 1; d < MAXBLKS; d <<= 1) {
        int v = 0;
        if (t < MAXBLKS && t >= d) v = bs[t - d];
        __syncthreads();
        if (t < MAXBLKS) bs[t] += v;
        __syncthreads();
    }
    int base = (b == 0) ? 0 : bs[b - 1];
    int i = b * SCAN_CHUNK + t;
    int v = (i < n) ? cnt[i] : 0;
    s[t] = v;
    __syncthreads();
    for (int d = 1; d < 1024; d <<= 1) {
        int u = (t >= d) ? s[t - d] : 0;
        __syncthreads();
        s[t] += u;
        __syncthreads();
    }
    if (i < n) {
        int e = base + s[t] - v;
        off[i] = e;
        cursor[i] = e;
    }
}

__global__ void scatter_kernel(const void* __restrict__ ei,
                               int* __restrict__ cursor, int* __restrict__ adj, int E) {
    int e = blockIdx.x * blockDim.x + threadIdx.x;
    if (e >= E) return;
    int d = load_idx(ei, (size_t)E + e);
    int s = load_idx(ei, e);
    int pos = atomicAdd(&cursor[d], 1);
    adj[pos] = s;
}

// ---------------------------------------------------------------------------
// temporal weight fold (Wcat [384,128] fp32)
// ---------------------------------------------------------------------------
__global__ void wcombine_kernel(const float* __restrict__ W0,
                                const float* __restrict__ Wp,
                                const float* __restrict__ WT,
                                float* __restrict__ Wcat) {
    int row = blockIdx.x;
    int m   = blockIdx.y;
    int col = threadIdx.x;
    __shared__ float L[128];
    const float* Lsrc = (m == 0) ? W0 : (Wp + (size_t)(m - 1) * 128 * 128);
    L[col] = Lsrc[row * 128 + col];
    __syncthreads();
    float s = 0.f;
#pragma unroll 8
    for (int k = 0; k < 128; k++)
        s = fmaf(L[k], WT[(size_t)(128 + k) * 128 + col], s);
    s *= (1.0f / 3.0f);
    if (m == 0) s += WT[(size_t)row * 128 + col];
    Wcat[(size_t)(m * 128 + row) * 128 + col] = s;
}

// ---------------------------------------------------------------------------
// bake W [K,128] fp32 -> fragment-order bf16 planes (hi at 0, lo at 128*K u16)
// ---------------------------------------------------------------------------
__global__ void wprep_kernel(const float* __restrict__ W, uint16_t* __restrict__ img, int K) {
    int idx = blockIdx.x * blockDim.x + threadIdx.x;
    if (idx >= 128 * K) return;
    int nn = idx / K, k = idx % K;
    float x = W[(size_t)k * 128 + nn];
    __nv_bfloat16 h = __float2bfloat16_rn(x);
    float hf = __bfloat162float(h);
    __nv_bfloat16 l = __float2bfloat16_rn(x - hf);
    int ks = k >> 4, kin = k & 15;
    int tig = (kin >> 1) & 3, w = kin >> 3, half = kin & 1;
    size_t u16pos = (size_t)((((ks * 128 + nn) * 4 + tig) * 2 + w) * 2 + half);
    img[u16pos]                     = *(uint16_t*)&h;
    img[(size_t)128 * K + u16pos]   = *(uint16_t*)&l;
}

// ---------------------------------------------------------------------------
// GEMM smem layout constants (dynamic smem, 56KB/CTA, 2 CTA/SM)
// ---------------------------------------------------------------------------
#define AS_STRIDE 20
#define AS_WORDS  (128 * AS_STRIDE)      // 2560
#define BS_WORDS  1024
#define SM_ASHI   0
#define SM_ASLO   (2 * AS_WORDS)
#define SM_BSHI   (4 * AS_WORDS)
#define SM_BSLO   (4 * AS_WORDS + 2 * BS_WORDS)
#define SM_TOTAL_BYTES ((4 * AS_WORDS + 4 * BS_WORDS) * 4)   // 57344

// ---------------------------------------------------------------------------
// FUSED sage layer: phase 1 gathers this CTA's 128 agg rows (CSR mean),
// phase 2 = GEMM OUT = relu([H | AGG] @ W), K=256.
// rows >= numTail are written ONLY to tail (when tail != nullptr)
// ---------------------------------------------------------------------------
__global__ __launch_bounds__(256, 2)
void gemm_sage_fused(const float* __restrict__ H, float* __restrict__ AGG,
                     const int* __restrict__ adj, const int* __restrict__ off,
                     const int* __restrict__ cnt,
                     const uint32_t* __restrict__ Bt,
                     float* __restrict__ OUT, float* __restrict__ tail,
                     int n, int numTail) {
    extern __shared__ uint32_t sm[];
    uint32_t* as_hi = sm + SM_ASHI;
    uint32_t* as_lo = sm + SM_ASLO;
    uint32_t* bs_hi = sm + SM_BSHI;
    uint32_t* bs_lo = sm + SM_BSLO;

    const int K = 256;
    const int KW = K * 64;               // words per B plane
    const int tid  = threadIdx.x;
    const int lane = tid & 31;
    const int wid  = tid >> 5;
    const int wm   = wid & 3;
    const int wn   = wid >> 2;
    const int rowBase = blockIdx.x * 128;

    // ---------------- phase 1: gather agg for this CTA's rows ----------------
    {
#pragma unroll 1
        for (int j = 0; j < 16; j++) {
            int node = rowBase + wid * 16 + j;
            if (node >= n) break;
            const int start = off[node];
            const int deg   = cnt[node];
            float ax = 0.f, ay = 0.f, az = 0.f, aw = 0.f;
            int i = 0;
            for (; i + 4 <= deg; i += 4) {
                int s0 = adj[start + i + 0];
                int s1 = adj[start + i + 1];
                int s2 = adj[start + i + 2];
                int s3 = adj[start + i + 3];
                float4 v0 = *(const float4*)&H[(size_t)s0 * D128 + lane * 4];
                float4 v1 = *(const float4*)&H[(size_t)s1 * D128 + lane * 4];
                float4 v2 = *(const float4*)&H[(size_t)s2 * D128 + lane * 4];
                float4 v3 = *(const float4*)&H[(size_t)s3 * D128 + lane * 4];
                ax += (v0.x + v1.x) + (v2.x + v3.x);
                ay += (v0.y + v1.y) + (v2.y + v3.y);
                az += (v0.z + v1.z) + (v2.z + v3.z);
                aw += (v0.w + v1.w) + (v2.w + v3.w);
            }
            for (; i < deg; i++) {
                int s = adj[start + i];
                float4 v = *(const float4*)&H[(size_t)s * D128 + lane * 4];
                ax += v.x; ay += v.y; az += v.z; aw += v.w;
            }
            float sc = 1.0f / (float)(deg > 1 ? deg : 1);
            *(float4*)&AGG[(size_t)node * D128 + lane * 4] =
                make_float4(ax * sc, ay * sc, az * sc, aw * sc);
        }
    }
    __syncthreads();   // global writes visible block-wide after this

    // ---------------- phase 2: GEMM ----------------
    const int arow = tid >> 1;
    const int ahalf = tid & 1;           // k offset = ahalf*8 elements
    const int grow = rowBase + arow;
    const bool rv  = grow < n;
    const float* hptr = H   + (size_t)(rv ? grow : 0) * D128;
    const float* aptr = AGG + (size_t)(rv ? grow : 0) * D128;

    float acc[2][8][4];
#pragma unroll
    for (int mt = 0; mt < 2; mt++)
#pragma unroll
        for (int nt = 0; nt < 8; nt++)
#pragma unroll
            for (int q = 0; q < 4; q++) acc[mt][nt][q] = 0.f;

    float4 pa, pb;
    uint4  pbh, pbl;
    {
        pa = rv ? *(const float4*)&hptr[ahalf * 8]     : make_float4(0, 0, 0, 0);
        pb = rv ? *(const float4*)&hptr[ahalf * 8 + 4] : make_float4(0, 0, 0, 0);
        pbh = *(const uint4*)&Bt[tid * 4];
        pbl = *(const uint4*)&Bt[KW + tid * 4];
    }

    int stage = 0;
    const int NK = K / 16;
#pragma unroll 1
    for (int ks = 0; ks < NK; ks++) {
        {
            uint32_t h0, l0, h1, l1, h2, l2, h3, l3;
            split2(pa.x, pa.y, h0, l0);
            split2(pa.z, pa.w, h1, l1);
            split2(pb.x, pb.y, h2, l2);
            split2(pb.z, pb.w, h3, l3);
            int aw = stage * AS_WORDS + arow * AS_STRIDE + ahalf * 4;
            *(uint4*)&as_hi[aw] = make_uint4(h0, h1, h2, h3);
            *(uint4*)&as_lo[aw] = make_uint4(l0, l1, l2, l3);
            int bw = stage * BS_WORDS + tid * 4;
            *(uint4*)&bs_hi[bw] = pbh;
            *(uint4*)&bs_lo[bw] = pbl;
        }
        __syncthreads();
        if (ks + 1 < NK) {
            int kb = (ks + 1) * 16;
            if (rv) {
                const float* s = (kb < 128) ? (hptr + kb) : (aptr + kb - 128);
                pa = *(const float4*)&s[ahalf * 8];
                pb = *(const float4*)&s[ahalf * 8 + 4];
            }
            pbh = *(const uint4*)&Bt[(ks + 1) * BS_WORDS + tid * 4];
            pbl = *(const uint4*)&Bt[KW + (ks + 1) * BS_WORDS + tid * 4];
        }
        {
            const int r = lane >> 2;
            const int p = lane & 3;
            uint32_t ah[2][4], al[2][4];
#pragma unroll
            for (int mt = 0; mt < 2; mt++) {
                int ab = stage * AS_WORDS + (wm * 32 + mt * 16 + r) * AS_STRIDE + p;
                ah[mt][0] = as_hi[ab];
                ah[mt][1] = as_hi[ab + 8 * AS_STRIDE];
                ah[mt][2] = as_hi[ab + 4];
                ah[mt][3] = as_hi[ab + 8 * AS_STRIDE + 4];
                al[mt][0] = as_lo[ab];
                al[mt][1] = as_lo[ab + 8 * AS_STRIDE];
                al[mt][2] = as_lo[ab + 4];
                al[mt][3] = as_lo[ab + 8 * AS_STRIDE + 4];
            }
#pragma unroll
            for (int nt = 0; nt < 8; nt++) {
                int nn = wn * 64 + nt * 8 + r;
                uint2 th = *(const uint2*)&bs_hi[stage * BS_WORDS + (nn * 4 + p) * 2];
                uint2 tl = *(const uint2*)&bs_lo[stage * BS_WORDS + (nn * 4 + p) * 2];
                uint32_t bh2[2] = {th.x, th.y};
                uint32_t bl2[2] = {tl.x, tl.y};
#pragma unroll
                for (int mt = 0; mt < 2; mt++) {
                    mma16816(acc[mt][nt], ah[mt], bh2);
                    mma16816(acc[mt][nt], ah[mt], bl2);
                    mma16816(acc[mt][nt], al[mt], bh2);
                }
            }
        }
        stage ^= 1;
    }

    const int r  = lane >> 2;
    const int c2 = (lane & 3) * 2;
#pragma unroll
    for (int mt = 0; mt < 2; mt++) {
#pragma unroll
        for (int half = 0; half < 2; half++) {
            int row = rowBase + wm * 32 + mt * 16 + half * 8 + r;
            if (row >= n) continue;
            float* dstp = (tail != nullptr && row >= numTail) ? tail : OUT;
#pragma unroll
            for (int nt = 0; nt < 8; nt++) {
                int col = wn * 64 + nt * 8 + c2;
                float2 o;
                o.x = fmaxf(acc[mt][nt][half * 2 + 0], 0.f);
                o.y = fmaxf(acc[mt][nt][half * 2 + 1], 0.f);
                *(float2*)&dstp[(size_t)row * D128 + col] = o;
            }
        }
    }
}

// ---------------------------------------------------------------------------
// final fused GEMM: f = leakyrelu([F2|P0|P1] @ Wcat, 0.2)
//                   out = f / max(||f||, 1e-12) ;  K = 384
// ---------------------------------------------------------------------------
__global__ __launch_bounds__(256, 2)
void gemm_final_mma(const float* __restrict__ F2, const float* __restrict__ P0,
                    const float* __restrict__ P1, const uint32_t* __restrict__ Bt,
                    float* __restrict__ OUT, int num) {
    extern __shared__ uint32_t sm[];
    uint32_t* as_hi = sm + SM_ASHI;
    uint32_t* as_lo = sm + SM_ASLO;
    uint32_t* bs_hi = sm + SM_BSHI;
    uint32_t* bs_lo = sm + SM_BSLO;
    __shared__ float ssbuf[2][128];

    const int K = 384;
    const int KW = K * 64;
    const int tid  = threadIdx.x;
    const int lane = tid & 31;
    const int wid  = tid >> 5;
    const int wm   = wid & 3;
    const int wn   = wid >> 2;
    const int rowBase = blockIdx.x * 128;

    const int arow = tid >> 1;
    const int ahalf = tid & 1;
    const int grow = rowBase + arow;
    const bool rv  = grow < num;
    const size_t ro = (size_t)(rv ? grow : 0) * D128;

    float acc[2][8][4];
#pragma unroll
    for (int mt = 0; mt < 2; mt++)
#pragma unroll
        for (int nt = 0; nt < 8; nt++)
#pragma unroll
            for (int q = 0; q < 4; q++) acc[mt][nt][q] = 0.f;

    float4 pa, pb;
    uint4  pbh, pbl;
    {
        pa = rv ? *(const float4*)&F2[ro + ahalf * 8]     : make_float4(0, 0, 0, 0);
        pb = rv ? *(const float4*)&F2[ro + ahalf * 8 + 4] : make_float4(0, 0, 0, 0);
        pbh = *(const uint4*)&Bt[tid * 4];
        pbl = *(const uint4*)&Bt[KW + tid * 4];
    }

    int stage = 0;
    const int NK = K / 16;
#pragma unroll 1
    for (int ks = 0; ks < NK; ks++) {
        {
            uint32_t h0, l0, h1, l1, h2, l2, h3, l3;
            split2(pa.x, pa.y, h0, l0);
            split2(pa.z, pa.w, h1, l1);
            split2(pb.x, pb.y, h2, l2);
            split2(pb.z, pb.w, h3, l3);
            int aw = stage * AS_WORDS + arow * AS_STRIDE + ahalf * 4;
            *(uint4*)&as_hi[aw] = make_uint4(h0, h1, h2, h3);
            *(uint4*)&as_lo[aw] = make_uint4(l0, l1, l2, l3);
            int bw = stage * BS_WORDS + tid * 4;
            *(uint4*)&bs_hi[bw] = pbh;
            *(uint4*)&bs_lo[bw] = pbl;
        }
        __syncthreads();
        if (ks + 1 < NK) {
            int kb = (ks + 1) * 16;
            if (rv) {
                const float* s = (kb < 128) ? (F2 + ro + kb)
                               : (kb < 256) ? (P0 + ro + kb - 128)
                                            : (P1 + ro + kb - 256);
                pa = *(const float4*)&s[ahalf * 8];
                pb = *(const float4*)&s[ahalf * 8 + 4];
            }
            pbh = *(const uint4*)&Bt[(ks + 1) * BS_WORDS + tid * 4];
            pbl = *(const uint4*)&Bt[KW + (ks + 1) * BS_WORDS + tid * 4];
        }
        {
            const int r = lane >> 2;
            const int p = lane & 3;
            uint32_t ah[2][4], al[2][4];
#pragma unroll
            for (int mt = 0; mt < 2; mt++) {
                int ab = stage * AS_WORDS + (wm * 32 + mt * 16 + r) * AS_STRIDE + p;
                ah[mt][0] = as_hi[ab];
                ah[mt][1] = as_hi[ab + 8 * AS_STRIDE];
                ah[mt][2] = as_hi[ab + 4];
                ah[mt][3] = as_hi[ab + 8 * AS_STRIDE + 4];
                al[mt][0] = as_lo[ab];
                al[mt][1] = as_lo[ab + 8 * AS_STRIDE];
                al[mt][2] = as_lo[ab + 4];
                al[mt][3] = as_lo[ab + 8 * AS_STRIDE + 4];
            }
#pragma unroll
            for (int nt = 0; nt < 8; nt++) {
                int nn = wn * 64 + nt * 8 + r;
                uint2 th = *(const uint2*)&bs_hi[stage * BS_WORDS + (nn * 4 + p) * 2];
                uint2 tl = *(const uint2*)&bs_lo[stage * BS_WORDS + (nn * 4 + p) * 2];
                uint32_t bh2[2] = {th.x, th.y};
                uint32_t bl2[2] = {tl.x, tl.y};
#pragma unroll
                for (int mt = 0; mt < 2; mt++) {
                    mma16816(acc[mt][nt], ah[mt], bh2);
                    mma16816(acc[mt][nt], ah[mt], bl2);
                    mma16816(acc[mt][nt], al[mt], bh2);
                }
            }
        }
        stage ^= 1;
    }

    const int r = lane >> 2;
    float ss[2][2] = {{0.f, 0.f}, {0.f, 0.f}};
#pragma unroll
    for (int mt = 0; mt < 2; mt++)
#pragma unroll
        for (int nt = 0; nt < 8; nt++)
#pragma unroll
            for (int q = 0; q < 4; q++) {
                float v = acc[mt][nt][q];
                v = (v > 0.f) ? v : 0.2f * v;
                acc[mt][nt][q] = v;
                ss[mt][q >> 1] = fmaf(v, v, ss[mt][q >> 1]);
            }
#pragma unroll
    for (int m = 1; m < 4; m <<= 1) {
#pragma unroll
        for (int mt = 0; mt < 2; mt++) {
            ss[mt][0] += __shfl_xor_sync(0xffffffffu, ss[mt][0], m);
            ss[mt][1] += __shfl_xor_sync(0xffffffffu, ss[mt][1], m);
        }
    }
    if ((lane & 3) == 0) {
#pragma unroll
        for (int mt = 0; mt < 2; mt++)
#pragma unroll
            for (int half = 0; half < 2; half++)
                ssbuf[wn][wm * 32 + mt * 16 + half * 8 + r] = ss[mt][half];
    }
    __syncthreads();

    const int c2 = (lane & 3) * 2;
#pragma unroll
    for (int mt = 0; mt < 2; mt++) {
#pragma unroll
        for (int half = 0; half < 2; half++) {
            int rl  = wm * 32 + mt * 16 + half * 8 + r;
            int row = rowBase + rl;
            if (row >= num) continue;
            float tot = ssbuf[0][rl] + ssbuf[1][rl];
            float inv = 1.0f / fmaxf(sqrtf(tot), 1e-12f);
#pragma unroll
            for (int nt = 0; nt < 8; nt++) {
                int col = wn * 64 + nt * 8 + c2;
                float2 o;
                o.x = acc[mt][nt][half * 2 + 0] * inv;
                o.y = acc[mt][nt][half * 2 + 1] * inv;
                *(float2*)&OUT[(size_t)row * D128 + col] = o;
            }
        }
    }
}

// ---------------------------------------------------------------------------
// launch (side stream overlaps weight prep with the CSR chain)
// ---------------------------------------------------------------------------
extern "C" void kernel_launch(void* const* d_in, const int* in_sizes, int n_in,
                              void* d_out, int out_size) {
    const float* x    = (const float*)d_in[0];
    const float* past = (const float*)d_in[1];
    const float* W1   = (const float*)d_in[2];
    const float* W2   = (const float*)d_in[3];
    const float* W0   = (const float*)d_in[4];
    const float* Wp   = (const float*)d_in[5];
    const float* WT   = (const float*)d_in[6];
    const void*  ei   = d_in[7];
    float*       out  = (float*)d_out;

    const int n   = in_sizes[0] / D128;
    const int num = in_sizes[1] / (2 * D128);
    const int E   = in_sizes[7] / 2;

    const float* p0 = past;
    const float* p1 = past + (size_t)num * D128;

    float *agg, *feat1, *feat2, *Wcat;
    int *cnt, *off, *cursor, *adj, *bsum;
    uint16_t *B1, *B2, *Bf;
    cudaGetSymbolAddress((void**)&agg,    g_agg);
    cudaGetSymbolAddress((void**)&feat1,  g_feat1);
    cudaGetSymbolAddress((void**)&feat2,  g_feat2);
    cudaGetSymbolAddress((void**)&cnt,    g_cnt);
    cudaGetSymbolAddress((void**)&off,    g_off);
    cudaGetSymbolAddress((void**)&cursor, g_cursor);
    cudaGetSymbolAddress((void**)&adj,    g_adj);
    cudaGetSymbolAddress((void**)&bsum,   g_blocksum);
    cudaGetSymbolAddress((void**)&Wcat,   g_Wcat);
    cudaGetSymbolAddress((void**)&B1,     g_B1);
    cudaGetSymbolAddress((void**)&B2,     g_B2);
    cudaGetSymbolAddress((void**)&Bf,     g_Bf);

    cudaFuncSetAttribute(gemm_sage_fused, cudaFuncAttributeMaxDynamicSharedMemorySize, SM_TOTAL_BYTES);
    cudaFuncSetAttribute(gemm_final_mma,  cudaFuncAttributeMaxDynamicSharedMemorySize, SM_TOTAL_BYTES);

    // persistent side stream + events (created once; identical graph each capture)
    static cudaStream_t s_side = nullptr;
    static cudaEvent_t  s_evFork = nullptr, s_evJoin = nullptr;
    if (s_side == nullptr) {
        cudaStreamCreateWithFlags(&s_side, cudaStreamNonBlocking);
        cudaEventCreateWithFlags(&s_evFork, cudaEventDisableTiming);
        cudaEventCreateWithFlags(&s_evJoin, cudaEventDisableTiming);
    }

    // fork: weight prep on side stream (independent of CSR chain)
    cudaEventRecord(s_evFork, 0);
    cudaStreamWaitEvent(s_side, s_evFork, 0);
    {
        dim3 g(128, 3);
        wcombine_kernel<<<g, 128, 0, s_side>>>(W0, Wp, WT, Wcat);
    }
    wprep_kernel<<<(128 * 256 + 255) / 256, 256, 0, s_side>>>(W1, B1, 256);
    wprep_kernel<<<(128 * 256 + 255) / 256, 256, 0, s_side>>>(W2, B2, 256);
    wprep_kernel<<<(128 * 384 + 255) / 256, 256, 0, s_side>>>(Wcat, Bf, 384);
    cudaEventRecord(s_evJoin, s_side);

    // main stream: CSR build
    zdetect_kernel<<<(n + 255) / 256, 256>>>((const int*)ei, cnt, E, n);
    deg_kernel<<<(E + 255) / 256, 256>>>(ei, cnt, E);
    const int scanBlocks = (n + SCAN_CHUNK - 1) / SCAN_CHUNK;
    scan_p1<<<scanBlocks, 1024>>>(cnt, bsum, n);
    scan_p3<<<scanBlocks, 1024>>>(cnt, bsum, off, cursor, n, scanBlocks);
    scatter_kernel<<<(E + 255) / 256, 256>>>(ei, cursor, adj, E);

    // join: GEMMs need baked weights
    cudaStreamWaitEvent(0, s_evJoin, 0);

    const int gemmBlocks = (n + 127) / 128;

    // layer 1 (fused gather + GEMM)
    gemm_sage_fused<<<gemmBlocks, 256, SM_TOTAL_BYTES>>>(x, agg, adj, off, cnt,
                                                         (const uint32_t*)B1,
                                                         feat1, nullptr, n, n);
    // layer 2 (fused; tail rows >= num go straight into d_out only)
    gemm_sage_fused<<<gemmBlocks, 256, SM_TOTAL_BYTES>>>(feat1, agg, adj, off, cnt,
                                                         (const uint32_t*)B2,
                                                         feat2, out, n, num);
    // fused final
    gemm_final_mma<<<(num + 127) / 128, 256, SM_TOTAL_BYTES>>>(feat2, p0, p1,
                                                               (const uint32_t*)Bf, out, num);
}

// round 11
// speedup vs baseline: 1.2842x; 1.2842x over previous
#include <cuda_runtime.h>
#include <cuda_bf16.h>
#include <cstddef>
#include <cstdint>

// ---------------------------------------------------------------------------
// dygraphSAGE on GB300 (base sm_103 target): CSR-gather aggregation +
// mma.sync bf16 hi/lo GEMMs (fragment-baked B, conflict-free smem, 2 CTA/SM)
// + chunked cross-stream gather/GEMM pipelining
// ---------------------------------------------------------------------------

#define D128 128
#define MAXN 131072
#define MAXE 2097152
#define SCAN_CHUNK 1024
#define MAXBLKS (MAXN / SCAN_CHUNK)   // 128

// scratch (device globals -- allocation-free per harness rules)
__device__ float g_agg  [(size_t)MAXN * D128];
__device__ float g_feat1[(size_t)MAXN * D128];
__device__ float g_feat2[(size_t)MAXN * D128];
__device__ int   g_cnt[MAXN];
__device__ int   g_off[MAXN];
__device__ int   g_cursor[MAXN];
__device__ int   g_adj[MAXE];
__device__ int   g_blocksum[MAXBLKS];
__device__ float g_Wcat[384 * D128];
__device__ int   g_is64;
// fragment-order baked weights: per plane (hi, lo): word idx
// ((ks*128 + nn)*4 + tig)*2 + w   (uint32 words, 2 bf16 each)
__device__ __align__(16) uint16_t g_B1[2 * 128 * 256];
__device__ __align__(16) uint16_t g_B2[2 * 128 * 256];
__device__ __align__(16) uint16_t g_Bf[2 * 128 * 384];

// ---------------------------------------------------------------------------
// helpers
// ---------------------------------------------------------------------------
__device__ __forceinline__ void split2(float x0, float x1, uint32_t& hi, uint32_t& lo) {
    asm("cvt.rn.bf16x2.f32 %0, %1, %2;" : "=r"(hi) : "f"(x1), "f"(x0));
    float h0 = __uint_as_float(hi << 16);
    float h1 = __uint_as_float(hi & 0xffff0000u);
    asm("cvt.rn.bf16x2.f32 %0, %1, %2;" : "=r"(lo) : "f"(x1 - h1), "f"(x0 - h0));
}

__device__ __forceinline__ void mma16816(float* c, const uint32_t* a, const uint32_t* b) {
    asm volatile("mma.sync.aligned.m16n8k16.row.col.f32.bf16.bf16.f32 "
                 "{%0,%1,%2,%3}, {%4,%5,%6,%7}, {%8,%9}, {%0,%1,%2,%3};"
                 : "+f"(c[0]), "+f"(c[1]), "+f"(c[2]), "+f"(c[3])
                 : "r"(a[0]), "r"(a[1]), "r"(a[2]), "r"(a[3]),
                   "r"(b[0]), "r"(b[1]));
}

// ---------------------------------------------------------------------------
// zero cnt + detect index dtype (block 0 samples)
// ---------------------------------------------------------------------------
__global__ void zdetect_kernel(const int* __restrict__ ei, int* __restrict__ cnt,
                               int E, int n) {
    int i = blockIdx.x * blockDim.x + threadIdx.x;
    if (i < n) cnt[i] = 0;
    if (blockIdx.x == 0) {
        __shared__ int any;
        if (threadIdx.x == 0) any = 0;
        __syncthreads();
        int c = E < 4096 ? E : 4096;
        for (int j = threadIdx.x; j < c; j += blockDim.x)
            if (ei[2 * j + 1] != 0) any = 1;
        __syncthreads();
        if (threadIdx.x == 0) g_is64 = any ? 0 : 1;
    }
}

__device__ __forceinline__ int load_idx(const void* ei, size_t pos) {
    return g_is64 ? (int)((const long long*)ei)[pos] : ((const int*)ei)[pos];
}

__global__ void deg_kernel(const void* __restrict__ ei, int* __restrict__ cnt, int E) {
    int e = blockIdx.x * blockDim.x + threadIdx.x;
    if (e < E) atomicAdd(&cnt[load_idx(ei, (size_t)E + e)], 1);
}

// ---------------------------------------------------------------------------
// 2-phase parallel exclusive scan of cnt -> off (+ cursor copy)
// ---------------------------------------------------------------------------
__global__ void scan_p1(const int* __restrict__ cnt, int* __restrict__ blocksum, int n) {
    __shared__ int red[1024];
    int b = blockIdx.x, t = threadIdx.x;
    int i = b * SCAN_CHUNK + t;
    red[t] = (i < n) ? cnt[i] : 0;
    __syncthreads();
    for (int d = 512; d > 0; d >>= 1) {
        if (t < d) red[t] += red[t + d];
        __syncthreads();
    }
    if (t == 0) blocksum[b] = red[0];
}

__global__ void scan_p3(const int* __restrict__ cnt, const int* __restrict__ blocksum,
                        int* __restrict__ off, int* __restrict__ cursor, int n, int B) {
    __shared__ int s[1024];
    __shared__ int bs[MAXBLKS];
    int b = blockIdx.x, t = threadIdx.x;
    if (t < MAXBLKS) bs[t] = (t < B) ? blocksum[t] : 0;
    __syncthreads();
    for (int d = 1; d < MAXBLKS; d <<= 1) {
        int v = 0;
        if (t < MAXBLKS && t >= d) v = bs[t - d];
        __syncthreads();
        if (t < MAXBLKS) bs[t] += v;
        __syncthreads();
    }
    int base = (b == 0) ? 0 : bs[b - 1];
    int i = b * SCAN_CHUNK + t;
    int v = (i < n) ? cnt[i] : 0;
    s[t] = v;
    __syncthreads();
    for (int d = 1; d < 1024; d <<= 1) {
        int u = (t >= d) ? s[t - d] : 0;
        __syncthreads();
        s[t] += u;
        __syncthreads();
    }
    if (i < n) {
        int e = base + s[t] - v;
        off[i] = e;
        cursor[i] = e;
    }
}

__global__ void scatter_kernel(const void* __restrict__ ei,
                               int* __restrict__ cursor, int* __restrict__ adj, int E) {
    int e = blockIdx.x * blockDim.x + threadIdx.x;
    if (e >= E) return;
    int d = load_idx(ei, (size_t)E + e);
    int s = load_idx(ei, e);
    int pos = atomicAdd(&cursor[d], 1);
    adj[pos] = s;
}

// ---------------------------------------------------------------------------
// CSR gather mean-aggregation over node range [nodeStart, nodeEnd):
// one warp per node, lane owns 4 features. agg pre-scaled by 1/max(deg,1).
// ---------------------------------------------------------------------------
__global__ __launch_bounds__(256)
void gather_kernel(const float* __restrict__ feat, const int* __restrict__ adj,
                   const int* __restrict__ off, const int* __restrict__ cnt,
                   float* __restrict__ agg, int nodeStart, int nodeEnd) {
    int w    = nodeStart + (int)((blockIdx.x * (size_t)blockDim.x + threadIdx.x) >> 5);
    int lane = threadIdx.x & 31;
    if (w >= nodeEnd) return;
    const int start = off[w];
    const int deg   = cnt[w];
    float ax = 0.f, ay = 0.f, az = 0.f, aw = 0.f;
    int i = 0;
    for (; i + 4 <= deg; i += 4) {
        int s0 = adj[start + i + 0];
        int s1 = adj[start + i + 1];
        int s2 = adj[start + i + 2];
        int s3 = adj[start + i + 3];
        float4 v0 = *(const float4*)&feat[(size_t)s0 * D128 + lane * 4];
        float4 v1 = *(const float4*)&feat[(size_t)s1 * D128 + lane * 4];
        float4 v2 = *(const float4*)&feat[(size_t)s2 * D128 + lane * 4];
        float4 v3 = *(const float4*)&feat[(size_t)s3 * D128 + lane * 4];
        ax += (v0.x + v1.x) + (v2.x + v3.x);
        ay += (v0.y + v1.y) + (v2.y + v3.y);
        az += (v0.z + v1.z) + (v2.z + v3.z);
        aw += (v0.w + v1.w) + (v2.w + v3.w);
    }
    for (; i < deg; i++) {
        int s = adj[start + i];
        float4 v = *(const float4*)&feat[(size_t)s * D128 + lane * 4];
        ax += v.x; ay += v.y; az += v.z; aw += v.w;
    }
    float sc = 1.0f / (float)(deg > 1 ? deg : 1);
    float4 o = make_float4(ax * sc, ay * sc, az * sc, aw * sc);
    *(float4*)&agg[(size_t)w * D128 + lane * 4] = o;
}

// ---------------------------------------------------------------------------
// temporal weight fold (Wcat [384,128] fp32)
// ---------------------------------------------------------------------------
__global__ void wcombine_kernel(const float* __restrict__ W0,
                                const float* __restrict__ Wp,
                                const float* __restrict__ WT,
                                float* __restrict__ Wcat) {
    int row = blockIdx.x;
    int m   = blockIdx.y;
    int col = threadIdx.x;
    __shared__ float L[128];
    const float* Lsrc = (m == 0) ? W0 : (Wp + (size_t)(m - 1) * 128 * 128);
    L[col] = Lsrc[row * 128 + col];
    __syncthreads();
    float s = 0.f;
#pragma unroll 8
    for (int k = 0; k < 128; k++)
        s = fmaf(L[k], WT[(size_t)(128 + k) * 128 + col], s);
    s *= (1.0f / 3.0f);
    if (m == 0) s += WT[(size_t)row * 128 + col];
    Wcat[(size_t)(m * 128 + row) * 128 + col] = s;
}

// ---------------------------------------------------------------------------
// bake W [K,128] fp32 -> fragment-order bf16 planes (hi at 0, lo at 128*K u16)
// ---------------------------------------------------------------------------
__global__ void wprep_kernel(const float* __restrict__ W, uint16_t* __restrict__ img, int K) {
    int idx = blockIdx.x * blockDim.x + threadIdx.x;
    if (idx >= 128 * K) return;
    int nn = idx / K, k = idx % K;
    float x = W[(size_t)k * 128 + nn];
    __nv_bfloat16 h = __float2bfloat16_rn(x);
    float hf = __bfloat162float(h);
    __nv_bfloat16 l = __float2bfloat16_rn(x - hf);
    int ks = k >> 4, kin = k & 15;
    int tig = (kin >> 1) & 3, w = kin >> 3, half = kin & 1;
    size_t u16pos = (size_t)((((ks * 128 + nn) * 4 + tig) * 2 + w) * 2 + half);
    img[u16pos]                     = *(uint16_t*)&h;
    img[(size_t)128 * K + u16pos]   = *(uint16_t*)&l;
}

// ---------------------------------------------------------------------------
// GEMM smem layout constants (dynamic smem, 56KB/CTA, 2 CTA/SM)
// ---------------------------------------------------------------------------
#define AS_STRIDE 20
#define AS_WORDS  (128 * AS_STRIDE)      // 2560
#define BS_WORDS  1024
#define SM_ASHI   0
#define SM_ASLO   (2 * AS_WORDS)
#define SM_BSHI   (4 * AS_WORDS)
#define SM_BSLO   (4 * AS_WORDS + 2 * BS_WORDS)
#define SM_TOTAL_BYTES ((4 * AS_WORDS + 4 * BS_WORDS) * 4)   // 57344

// ---------------------------------------------------------------------------
// SAGE layer GEMM over rows [rowStart, rowStart + 128*gridDim.x):
// OUT = relu([H | AGG] @ W), K=256, AGG pre-scaled.
// rows >= numTail are written ONLY to tail (when tail != nullptr)
// ---------------------------------------------------------------------------
__global__ __launch_bounds__(256, 2)
void gemm_sage_mma(const float* __restrict__ H, const float* __restrict__ AGG,
                   const uint32_t* __restrict__ Bt,
                   float* __restrict__ OUT, float* __restrict__ tail,
                   int n, int numTail, int rowStart) {
    extern __shared__ uint32_t sm[];
    uint32_t* as_hi = sm + SM_ASHI;
    uint32_t* as_lo = sm + SM_ASLO;
    uint32_t* bs_hi = sm + SM_BSHI;
    uint32_t* bs_lo = sm + SM_BSLO;

    const int K = 256;
    const int KW = K * 64;               // words per B plane
    const int tid  = threadIdx.x;
    const int lane = tid & 31;
    const int wid  = tid >> 5;
    const int wm   = wid & 3;
    const int wn   = wid >> 2;
    const int rowBase = rowStart + blockIdx.x * 128;

    const int arow = tid >> 1;
    const int ahalf = tid & 1;           // k offset = ahalf*8 elements
    const int grow = rowBase + arow;
    const bool rv  = grow < n;
    const float* hptr = H   + (size_t)(rv ? grow : 0) * D128;
    const float* aptr = AGG + (size_t)(rv ? grow : 0) * D128;

    float acc[2][8][4];
#pragma unroll
    for (int mt = 0; mt < 2; mt++)
#pragma unroll
        for (int nt = 0; nt < 8; nt++)
#pragma unroll
            for (int q = 0; q < 4; q++) acc[mt][nt][q] = 0.f;

    float4 pa, pb;
    uint4  pbh, pbl;
    {
        pa = rv ? *(const float4*)&hptr[ahalf * 8]     : make_float4(0, 0, 0, 0);
        pb = rv ? *(const float4*)&hptr[ahalf * 8 + 4] : make_float4(0, 0, 0, 0);
        pbh = *(const uint4*)&Bt[tid * 4];
        pbl = *(const uint4*)&Bt[KW + tid * 4];
    }

    int stage = 0;
    const int NK = K / 16;
#pragma unroll 1
    for (int ks = 0; ks < NK; ks++) {
        {
            uint32_t h0, l0, h1, l1, h2, l2, h3, l3;
            split2(pa.x, pa.y, h0, l0);
            split2(pa.z, pa.w, h1, l1);
            split2(pb.x, pb.y, h2, l2);
            split2(pb.z, pb.w, h3, l3);
            int aw = stage * AS_WORDS + arow * AS_STRIDE + ahalf * 4;
            *(uint4*)&as_hi[aw] = make_uint4(h0, h1, h2, h3);
            *(uint4*)&as_lo[aw] = make_uint4(l0, l1, l2, l3);
            int bw = stage * BS_WORDS + tid * 4;
            *(uint4*)&bs_hi[bw] = pbh;
            *(uint4*)&bs_lo[bw] = pbl;
        }
        __syncthreads();
        if (ks + 1 < NK) {
            int kb = (ks + 1) * 16;
            if (rv) {
                const float* s = (kb < 128) ? (hptr + kb) : (aptr + kb - 128);
                pa = *(const float4*)&s[ahalf * 8];
                pb = *(const float4*)&s[ahalf * 8 + 4];
            }
            pbh = *(const uint4*)&Bt[(ks + 1) * BS_WORDS + tid * 4];
            pbl = *(const uint4*)&Bt[KW + (ks + 1) * BS_WORDS + tid * 4];
        }
        {
            const int r = lane >> 2;
            const int p = lane & 3;
            uint32_t ah[2][4], al[2][4];
#pragma unroll
            for (int mt = 0; mt < 2; mt++) {
                int ab = stage * AS_WORDS + (wm * 32 + mt * 16 + r) * AS_STRIDE + p;
                ah[mt][0] = as_hi[ab];
                ah[mt][1] = as_hi[ab + 8 * AS_STRIDE];
                ah[mt][2] = as_hi[ab + 4];
                ah[mt][3] = as_hi[ab + 8 * AS_STRIDE + 4];
                al[mt][0] = as_lo[ab];
                al[mt][1] = as_lo[ab + 8 * AS_STRIDE];
                al[mt][2] = as_lo[ab + 4];
                al[mt][3] = as_lo[ab + 8 * AS_STRIDE + 4];
            }
#pragma unroll
            for (int nt = 0; nt < 8; nt++) {
                int nn = wn * 64 + nt * 8 + r;
                uint2 th = *(const uint2*)&bs_hi[stage * BS_WORDS + (nn * 4 + p) * 2];
                uint2 tl = *(const uint2*)&bs_lo[stage * BS_WORDS + (nn * 4 + p) * 2];
                uint32_t bh2[2] = {th.x, th.y};
                uint32_t bl2[2] = {tl.x, tl.y};
#pragma unroll
                for (int mt = 0; mt < 2; mt++) {
                    mma16816(acc[mt][nt], ah[mt], bh2);
                    mma16816(acc[mt][nt], ah[mt], bl2);
                    mma16816(acc[mt][nt], al[mt], bh2);
                }
            }
        }
        stage ^= 1;
    }

    const int r  = lane >> 2;
    const int c2 = (lane & 3) * 2;
#pragma unroll
    for (int mt = 0; mt < 2; mt++) {
#pragma unroll
        for (int half = 0; half < 2; half++) {
            int row = rowBase + wm * 32 + mt * 16 + half * 8 + r;
            if (row >= n) continue;
            float* dstp = (tail != nullptr && row >= numTail) ? tail : OUT;
#pragma unroll
            for (int nt = 0; nt < 8; nt++) {
                int col = wn * 64 + nt * 8 + c2;
                float2 o;
                o.x = fmaxf(acc[mt][nt][half * 2 + 0], 0.f);
                o.y = fmaxf(acc[mt][nt][half * 2 + 1], 0.f);
                *(float2*)&dstp[(size_t)row * D128 + col] = o;
            }
        }
    }
}

// ---------------------------------------------------------------------------
// final fused GEMM: f = leakyrelu([F2|P0|P1] @ Wcat, 0.2)
//                   out = f / max(||f||, 1e-12) ;  K = 384
// ---------------------------------------------------------------------------
__global__ __launch_bounds__(256, 2)
void gemm_final_mma(const float* __restrict__ F2, const float* __restrict__ P0,
                    const float* __restrict__ P1, const uint32_t* __restrict__ Bt,
                    float* __restrict__ OUT, int num) {
    extern __shared__ uint32_t sm[];
    uint32_t* as_hi = sm + SM_ASHI;
    uint32_t* as_lo = sm + SM_ASLO;
    uint32_t* bs_hi = sm + SM_BSHI;
    uint32_t* bs_lo = sm + SM_BSLO;
    __shared__ float ssbuf[2][128];

    const int K = 384;
    const int KW = K * 64;
    const int tid  = threadIdx.x;
    const int lane = tid & 31;
    const int wid  = tid >> 5;
    const int wm   = wid & 3;
    const int wn   = wid >> 2;
    const int rowBase = blockIdx.x * 128;

    const int arow = tid >> 1;
    const int ahalf = tid & 1;
    const int grow = rowBase + arow;
    const bool rv  = grow < num;
    const size_t ro = (size_t)(rv ? grow : 0) * D128;

    float acc[2][8][4];
#pragma unroll
    for (int mt = 0; mt < 2; mt++)
#pragma unroll
        for (int nt = 0; nt < 8; nt++)
#pragma unroll
            for (int q = 0; q < 4; q++) acc[mt][nt][q] = 0.f;

    float4 pa, pb;
    uint4  pbh, pbl;
    {
        pa = rv ? *(const float4*)&F2[ro + ahalf * 8]     : make_float4(0, 0, 0, 0);
        pb = rv ? *(const float4*)&F2[ro + ahalf * 8 + 4] : make_float4(0, 0, 0, 0);
        pbh = *(const uint4*)&Bt[tid * 4];
        pbl = *(const uint4*)&Bt[KW + tid * 4];
    }

    int stage = 0;
    const int NK = K / 16;
#pragma unroll 1
    for (int ks = 0; ks < NK; ks++) {
        {
            uint32_t h0, l0, h1, l1, h2, l2, h3, l3;
            split2(pa.x, pa.y, h0, l0);
            split2(pa.z, pa.w, h1, l1);
            split2(pb.x, pb.y, h2, l2);
            split2(pb.z, pb.w, h3, l3);
            int aw = stage * AS_WORDS + arow * AS_STRIDE + ahalf * 4;
            *(uint4*)&as_hi[aw] = make_uint4(h0, h1, h2, h3);
            *(uint4*)&as_lo[aw] = make_uint4(l0, l1, l2, l3);
            int bw = stage * BS_WORDS + tid * 4;
            *(uint4*)&bs_hi[bw] = pbh;
            *(uint4*)&bs_lo[bw] = pbl;
        }
        __syncthreads();
        if (ks + 1 < NK) {
            int kb = (ks + 1) * 16;
            if (rv) {
                const float* s = (kb < 128) ? (F2 + ro + kb)
                               : (kb < 256) ? (P0 + ro + kb - 128)
                                            : (P1 + ro + kb - 256);
                pa = *(const float4*)&s[ahalf * 8];
                pb = *(const float4*)&s[ahalf * 8 + 4];
            }
            pbh = *(const uint4*)&Bt[(ks + 1) * BS_WORDS + tid * 4];
            pbl = *(const uint4*)&Bt[KW + (ks + 1) * BS_WORDS + tid * 4];
        }
        {
            const int r = lane >> 2;
            const int p = lane & 3;
            uint32_t ah[2][4], al[2][4];
#pragma unroll
            for (int mt = 0; mt < 2; mt++) {
                int ab = stage * AS_WORDS + (wm * 32 + mt * 16 + r) * AS_STRIDE + p;
                ah[mt][0] = as_hi[ab];
                ah[mt][1] = as_hi[ab + 8 * AS_STRIDE];
                ah[mt][2] = as_hi[ab + 4];
                ah[mt][3] = as_hi[ab + 8 * AS_STRIDE + 4];
                al[mt][0] = as_lo[ab];
                al[mt][1] = as_lo[ab + 8 * AS_STRIDE];
                al[mt][2] = as_lo[ab + 4];
                al[mt][3] = as_lo[ab + 8 * AS_STRIDE + 4];
            }
#pragma unroll
            for (int nt = 0; nt < 8; nt++) {
                int nn = wn * 64 + nt * 8 + r;
                uint2 th = *(const uint2*)&bs_hi[stage * BS_WORDS + (nn * 4 + p) * 2];
                uint2 tl = *(const uint2*)&bs_lo[stage * BS_WORDS + (nn * 4 + p) * 2];
                uint32_t bh2[2] = {th.x, th.y};
                uint32_t bl2[2] = {tl.x, tl.y};
#pragma unroll
                for (int mt = 0; mt < 2; mt++) {
                    mma16816(acc[mt][nt], ah[mt], bh2);
                    mma16816(acc[mt][nt], ah[mt], bl2);
                    mma16816(acc[mt][nt], al[mt], bh2);
                }
            }
        }
        stage ^= 1;
    }

    const int r = lane >> 2;
    float ss[2][2] = {{0.f, 0.f}, {0.f, 0.f}};
#pragma unroll
    for (int mt = 0; mt < 2; mt++)
#pragma unroll
        for (int nt = 0; nt < 8; nt++)
#pragma unroll
            for (int q = 0; q < 4; q++) {
                float v = acc[mt][nt][q];
                v = (v > 0.f) ? v : 0.2f * v;
                acc[mt][nt][q] = v;
                ss[mt][q >> 1] = fmaf(v, v, ss[mt][q >> 1]);
            }
#pragma unroll
    for (int m = 1; m < 4; m <<= 1) {
#pragma unroll
        for (int mt = 0; mt < 2; mt++) {
            ss[mt][0] += __shfl_xor_sync(0xffffffffu, ss[mt][0], m);
            ss[mt][1] += __shfl_xor_sync(0xffffffffu, ss[mt][1], m);
        }
    }
    if ((lane & 3) == 0) {
#pragma unroll
        for (int mt = 0; mt < 2; mt++)
#pragma unroll
            for (int half = 0; half < 2; half++)
                ssbuf[wn][wm * 32 + mt * 16 + half * 8 + r] = ss[mt][half];
    }
    __syncthreads();

    const int c2 = (lane & 3) * 2;
#pragma unroll
    for (int mt = 0; mt < 2; mt++) {
#pragma unroll
        for (int half = 0; half < 2; half++) {
            int rl  = wm * 32 + mt * 16 + half * 8 + r;
            int row = rowBase + rl;
            if (row >= num) continue;
            float tot = ssbuf[0][rl] + ssbuf[1][rl];
            float inv = 1.0f / fmaxf(sqrtf(tot), 1e-12f);
#pragma unroll
            for (int nt = 0; nt < 8; nt++) {
                int col = wn * 64 + nt * 8 + c2;
                float2 o;
                o.x = acc[mt][nt][half * 2 + 0] * inv;
                o.y = acc[mt][nt][half * 2 + 1] * inv;
                *(float2*)&OUT[(size_t)row * D128 + col] = o;
            }
        }
    }
}

// ---------------------------------------------------------------------------
// launch: chunked cross-stream pipeline
//   stream0: CSR chain -> gatherA1 -> gatherB1 -> (evM1) gatherA2 -> gatherB2
//            -> gemm2 tail chunk (rows >= split2, into out)
//   s_b:     gemm1_A (after evGA1) -> gemm1_B (after evGB1) -> evM1
//            -> gemm2_A head (after evGA2) -> final gemm -> evFin
//   s_side:  weight bake -> evJoin
// ---------------------------------------------------------------------------
extern "C" void kernel_launch(void* const* d_in, const int* in_sizes, int n_in,
                              void* d_out, int out_size) {
    const float* x    = (const float*)d_in[0];
    const float* past = (const float*)d_in[1];
    const float* W1   = (const float*)d_in[2];
    const float* W2   = (const float*)d_in[3];
    const float* W0   = (const float*)d_in[4];
    const float* Wp   = (const float*)d_in[5];
    const float* WT   = (const float*)d_in[6];
    const void*  ei   = d_in[7];
    float*       out  = (float*)d_out;

    const int n   = in_sizes[0] / D128;
    const int num = in_sizes[1] / (2 * D128);
    const int E   = in_sizes[7] / 2;

    const float* p0 = past;
    const float* p1 = past + (size_t)num * D128;

    float *agg, *feat1, *feat2, *Wcat;
    int *cnt, *off, *cursor, *adj, *bsum;
    uint16_t *B1, *B2, *Bf;
    cudaGetSymbolAddress((void**)&agg,    g_agg);
    cudaGetSymbolAddress((void**)&feat1,  g_feat1);
    cudaGetSymbolAddress((void**)&feat2,  g_feat2);
    cudaGetSymbolAddress((void**)&cnt,    g_cnt);
    cudaGetSymbolAddress((void**)&off,    g_off);
    cudaGetSymbolAddress((void**)&cursor, g_cursor);
    cudaGetSymbolAddress((void**)&adj,    g_adj);
    cudaGetSymbolAddress((void**)&bsum,   g_blocksum);
    cudaGetSymbolAddress((void**)&Wcat,   g_Wcat);
    cudaGetSymbolAddress((void**)&B1,     g_B1);
    cudaGetSymbolAddress((void**)&B2,     g_B2);
    cudaGetSymbolAddress((void**)&Bf,     g_Bf);

    cudaFuncSetAttribute(gemm_sage_mma,  cudaFuncAttributeMaxDynamicSharedMemorySize, SM_TOTAL_BYTES);
    cudaFuncSetAttribute(gemm_final_mma, cudaFuncAttributeMaxDynamicSharedMemorySize, SM_TOTAL_BYTES);

    // persistent streams/events (created once; identical graph each capture)
    static cudaStream_t s_side = nullptr, s_b = nullptr;
    static cudaEvent_t evFork, evJoin, evGA1, evGB1, evM1, evGA2, evGB2, evFin;
    if (s_side == nullptr) {
        cudaStreamCreateWithFlags(&s_side, cudaStreamNonBlocking);
        cudaStreamCreateWithFlags(&s_b,    cudaStreamNonBlocking);
        cudaEventCreateWithFlags(&evFork, cudaEventDisableTiming);
        cudaEventCreateWithFlags(&evJoin, cudaEventDisableTiming);
        cudaEventCreateWithFlags(&evGA1,  cudaEventDisableTiming);
        cudaEventCreateWithFlags(&evGB1,  cudaEventDisableTiming);
        cudaEventCreateWithFlags(&evM1,   cudaEventDisableTiming);
        cudaEventCreateWithFlags(&evGA2,  cudaEventDisableTiming);
        cudaEventCreateWithFlags(&evGB2,  cudaEventDisableTiming);
        cudaEventCreateWithFlags(&evFin,  cudaEventDisableTiming);
    }

    // chunk geometry
    const int nBlocks    = (n + 127) / 128;
    const int blkA1      = (nBlocks + 1) / 2;          // layer-1 head blocks
    const int split1     = blkA1 * 128 < n ? blkA1 * 128 : n;
    const int blkB1      = nBlocks - blkA1;
    const int headBlocks = (num + 127) / 128;          // layer-2 head covers [0,num)
    const int split2     = headBlocks * 128 < n ? headBlocks * 128 : n;
    const int tailBlocks = nBlocks - headBlocks;

    // fork
    cudaEventRecord(evFork, 0);
    cudaStreamWaitEvent(s_side, evFork, 0);
    cudaStreamWaitEvent(s_b,    evFork, 0);

    // side: weight bake
    {
        dim3 g(128, 3);
        wcombine_kernel<<<g, 128, 0, s_side>>>(W0, Wp, WT, Wcat);
    }
    wprep_kernel<<<(128 * 256 + 255) / 256, 256, 0, s_side>>>(W1, B1, 256);
    wprep_kernel<<<(128 * 256 + 255) / 256, 256, 0, s_side>>>(W2, B2, 256);
    wprep_kernel<<<(128 * 384 + 255) / 256, 256, 0, s_side>>>(Wcat, Bf, 384);
    cudaEventRecord(evJoin, s_side);
    cudaStreamWaitEvent(s_b, evJoin, 0);   // gemms need weights

    // stream0: CSR build
    zdetect_kernel<<<(n + 255) / 256, 256>>>((const int*)ei, cnt, E, n);
    deg_kernel<<<(E + 255) / 256, 256>>>(ei, cnt, E);
    const int scanBlocks = (n + SCAN_CHUNK - 1) / SCAN_CHUNK;
    scan_p1<<<scanBlocks, 1024>>>(cnt, bsum, n);
    scan_p3<<<scanBlocks, 1024>>>(cnt, bsum, off, cursor, n, scanBlocks);
    scatter_kernel<<<(E + 255) / 256, 256>>>(ei, cursor, adj, E);

    // layer-1 gathers (chunked) on stream0
    gather_kernel<<<(split1 + 7) / 8, 256>>>(x, adj, off, cnt, agg, 0, split1);
    cudaEventRecord(evGA1, 0);
    if (n > split1) {
        gather_kernel<<<(n - split1 + 7) / 8, 256>>>(x, adj, off, cnt, agg, split1, n);
    }
    cudaEventRecord(evGB1, 0);

    // s_b: layer-1 GEMM chunks
    cudaStreamWaitEvent(s_b, evGA1, 0);
    gemm_sage_mma<<<blkA1, 256, SM_TOTAL_BYTES, s_b>>>(x, agg, (const uint32_t*)B1,
                                                       feat1, nullptr, n, n, 0);
    cudaStreamWaitEvent(s_b, evGB1, 0);
    if (blkB1 > 0)
        gemm_sage_mma<<<blkB1, 256, SM_TOTAL_BYTES, s_b>>>(x, agg, (const uint32_t*)B1,
                                                           feat1, nullptr, n, n, split1);
    cudaEventRecord(evM1, s_b);

    // stream0: layer-2 gathers (need all of feat1)
    cudaStreamWaitEvent(0, evM1, 0);
    gather_kernel<<<(split2 + 7) / 8, 256>>>(feat1, adj, off, cnt, agg, 0, split2);
    cudaEventRecord(evGA2, 0);
    if (n > split2) {
        gather_kernel<<<(n - split2 + 7) / 8, 256>>>(feat1, adj, off, cnt, agg, split2, n);
    }
    cudaEventRecord(evGB2, 0);

    // stream0: layer-2 tail GEMM (rows >= split2 >= num -> out only)
    cudaStreamWaitEvent(0, evJoin, 0);
    if (tailBlocks > 0)
        gemm_sage_mma<<<tailBlocks, 256, SM_TOTAL_BYTES>>>(feat1, agg, (const uint32_t*)B2,
                                                           feat2, out, n, num, split2);

    // s_b: layer-2 head GEMM + final (head covers all rows < num)
    cudaStreamWaitEvent(s_b, evGA2, 0);
    gemm_sage_mma<<<headBlocks, 256, SM_TOTAL_BYTES, s_b>>>(feat1, agg, (const uint32_t*)B2,
                                                            feat2, out, n, num, 0);
    gemm_final_mma<<<(num + 127) / 128, 256, SM_TOTAL_BYTES, s_b>>>(feat2, p0, p1,
                                                                    (const uint32_t*)Bf, out, num);
    cudaEventRecord(evFin, s_b);
    cudaStreamWaitEvent(0, evFin, 0);   // join everything back to origin stream
}